// round 17
// baseline (speedup 1.0000x reference)
#include <cuda_runtime.h>

// Problem constants
#define TT    1200              // time length
#define NF    10                // conv filters
#define KK    17                // conv kernel width (pad 8 both sides)
#define NSTR  240               // 5-wide output strips per row (1200/5)
#define NTP   76                // pooled length
#define NTPG  19                // groups of 4 pooled outputs (76/4)
#define FEAT  (NF*NTP)          // 760
#define ROWS  2                 // (b,m) rows per block (the f32x2 SIMD pair)
#define THREADS 256

typedef unsigned long long u64;

__device__ __forceinline__ u64 pack2(float lo, float hi) {
    u64 r;
    asm("mov.b64 %0, {%1, %2};" : "=l"(r) : "f"(lo), "f"(hi));
    return r;
}
__device__ __forceinline__ void unpack2(u64 v, float& lo, float& hi) {
    asm("mov.b64 {%0, %1}, %2;" : "=f"(lo), "=f"(hi) : "l"(v));
}
__device__ __forceinline__ u64 ffma2(u64 a, u64 b, u64 c) {
    u64 d;
    asm("fma.rn.f32x2 %0, %1, %2, %3;" : "=l"(d) : "l"(a), "l"(b), "l"(c));
    return d;
}

__global__ __launch_bounds__(THREADS, 2) void scorer_kernel(
    const float* __restrict__ x,       // (B,1,M,T) rows of 1200
    const float* __restrict__ conv_w,  // (NF,1,KK)
    const float* __restrict__ conv_b,  // (NF)
    const float* __restrict__ lin_w,   // (M, FEAT)
    const float* __restrict__ lin_b,   // (M)
    float* __restrict__ out)           // (B,M,1)
{
    __shared__ u64   s_x2[TT + 16];        // {row0,row1} pairs, 8-zero halo each side
    __shared__ u64   s_w2[NF * KK];        // {w,w}
    __shared__ u64   s_b2[NF];             // {b,b}
    __shared__ float s_S[ROWS][NF * NSTR]; // 5-strip sums of conv^2
    __shared__ __align__(16) float s_lin[ROWS][FEAT];  // lin_w rows for this block
    __shared__ float s_out[ROWS];

    const int tid  = threadIdx.x;
    const int row0 = blockIdx.x * ROWS;    // row = b*64 + m
    const int m0   = row0 & 63;

    // ---- Phase 0: stage weights, lin rows, halos, x rows (vectorized) ----
    for (int i = tid; i < NF * KK; i += THREADS) { float w = conv_w[i]; s_w2[i] = pack2(w, w); }
    if (tid < NF)   { float b = conv_b[tid]; s_b2[tid] = pack2(b, b); }
    if (tid < ROWS) s_out[tid] = 0.f;
    if (tid >= THREADS - 16) {
        int j = tid - (THREADS - 16);
        if (j < 8) s_x2[j] = 0ull;             // left halo
        else       s_x2[TT + j] = 0ull;        // right halo
    }
    {
        // lin_w rows (coalesced float4): 1520 floats = 380 float4
        const float4* l4 = (const float4*)(lin_w + (size_t)m0 * FEAT);
        float4* d4 = (float4*)&s_lin[0][0];    // rows contiguous (FEAT*ROWS floats)
        for (int i = tid; i < (ROWS * FEAT) / 4; i += THREADS) d4[i] = l4[i];
    }
    {
        // x rows: 300 float4 per row, packed into interleaved u64 pairs
        const float4* xr0 = (const float4*)(x + (size_t)row0 * TT);
        const float4* xr1 = (const float4*)(x + (size_t)(row0 + 1) * TT);
        for (int c = tid; c < TT / 4; c += THREADS) {
            const float4 a = xr0[c];
            const float4 b = xr1[c];
            const int t = 8 + 4 * c;
            s_x2[t    ] = pack2(a.x, b.x);
            s_x2[t + 1] = pack2(a.y, b.y);
            s_x2[t + 2] = pack2(a.z, b.z);
            s_x2[t + 3] = pack2(a.w, b.w);
        }
    }
    __syncthreads();

    // ---- Phase 1: per 5-output strip, ALL filters (exact R2 hot loop) ----
    if (tid < NSTR) {
        const int s = tid;
        const u64* xp = &s_x2[5 * s];          // window x[5s-8 .. 5s+12]
        u64 xv[21];
        #pragma unroll
        for (int j = 0; j < 21; ++j) xv[j] = xp[j];

        for (int f = 0; f < NF; ++f) {
            const u64* wp = &s_w2[f * KK];
            const u64 b2 = s_b2[f];
            u64 c0 = b2, c1 = b2, c2 = b2, c3 = b2, c4 = b2;
            #pragma unroll
            for (int k = 0; k < KK; ++k) {
                const u64 wk = wp[k];          // broadcast LDS.64
                c0 = ffma2(xv[k    ], wk, c0);
                c1 = ffma2(xv[k + 1], wk, c1);
                c2 = ffma2(xv[k + 2], wk, c2);
                c3 = ffma2(xv[k + 3], wk, c3);
                c4 = ffma2(xv[k + 4], wk, c4);
            }
            u64 S = ffma2(c0, c0, 0ull);       // {0,0} == {0.f,0.f}
            S = ffma2(c1, c1, S);
            S = ffma2(c2, c2, S);
            S = ffma2(c3, c3, S);
            S = ffma2(c4, c4, S);
            float S0, S1; unpack2(S, S0, S1);
            s_S[0][f * NSTR + s] = S0;
            s_S[1][f * NSTR + s] = S1;
        }
    }
    __syncthreads();

    // ---- Phase 2: sliding pool (15 strips per window, hop 3) -> log -> dot ----
    float part0 = 0.f, part1 = 0.f;
    for (int task = tid; task < ROWS * NF * NTPG; task += THREADS) {   // 380 tasks
        int r   = task / (NF * NTPG);
        int rem = task - r * (NF * NTPG);
        int f   = rem / NTPG;
        int g   = rem - f * NTPG;              // covers tp = 4g .. 4g+3

        const float* Sp = &s_S[r][f * NSTR + 12 * g];
        float sv[24];
        #pragma unroll
        for (int j = 0; j < 24; ++j) sv[j] = Sp[j];

        float run = 0.f;
        #pragma unroll
        for (int j = 0; j < 15; ++j) run += sv[j];

        const float4 lw = *(const float4*)&s_lin[r][f * NTP + 4 * g];
        float acc = 0.f;
        #pragma unroll
        for (int q = 0; q < 4; ++q) {
            float p = fmaxf(run * (1.0f / 75.0f), 1e-10f);
            float v = __logf(p);
            float w = (q == 0) ? lw.x : (q == 1) ? lw.y : (q == 2) ? lw.z : lw.w;
            acc = fmaf(v, w, acc);
            if (q < 3) {
                run += (sv[15 + 3*q] + sv[16 + 3*q] + sv[17 + 3*q])
                     - (sv[3*q] + sv[1 + 3*q] + sv[2 + 3*q]);
            }
        }
        if (r == 0) part0 += acc; else part1 += acc;
    }
    #pragma unroll
    for (int off = 16; off > 0; off >>= 1) {
        part0 += __shfl_down_sync(0xffffffffu, part0, off);
        part1 += __shfl_down_sync(0xffffffffu, part1, off);
    }
    if ((tid & 31) == 0) {
        atomicAdd(&s_out[0], part0);
        atomicAdd(&s_out[1], part1);
    }
    __syncthreads();

    if (tid < ROWS) out[row0 + tid] = s_out[tid] + lin_b[m0 + tid];
}

extern "C" void kernel_launch(void* const* d_in, const int* in_sizes, int n_in,
                              void* d_out, int out_size) {
    const float* x      = (const float*)d_in[0];
    const float* conv_w = (const float*)d_in[1];
    const float* conv_b = (const float*)d_in[2];
    const float* lin_w  = (const float*)d_in[3];
    const float* lin_b  = (const float*)d_in[4];
    float* out = (float*)d_out;

    const int n_rows = 256 * 64;               // B*M
    scorer_kernel<<<n_rows / ROWS, THREADS>>>(x, conv_w, conv_b, lin_w, lin_b, out);
}